// round 1
// baseline (speedup 1.0000x reference)
#include <cuda_runtime.h>
#include <cuda_fp16.h>
#include <mma.h>

using namespace nvcuda;

namespace {

constexpr int TILE_M  = 128;
constexpr int THREADS = 256;

// SMEM layout. All array offsets are multiples of 16B (ldmatrix alignment).
// act: activations, row-major, ld = 72 halfs (144B rows -> 16B aligned, odd
//      half-ld breaks the worst bank-conflict patterns).
// stage: fp32 accumulator staging between mma and relu/convert pass.
// w_*: weights as B operands, col-major (k fastest), ld padded by 8.
struct SmemLayout {
    __half act[TILE_M * 72];    // 18432 B
    float  stage[TILE_M * 64];  // 32768 B
    __half w_d0[64 * 40];       // K=32 (ld 40), N=64
    __half w_d1[16 * 72];       // K=64 (ld 72), N=16
    __half w_c0[64 * 40];       // K=31->32 (ld 40), N=64
    __half w_c1[64 * 72];       // K=64, N=64
    __half w_c2[64 * 72];       // K=64, N=64
    __half w_c3[16 * 72];       // K=64, N=3->16
    float  sigma[TILE_M];
};  // ~85 KB -> 2 CTAs / SM

// One layer: [128 x 16*KTILES] (act, fp16) @ [16*KTILES x 16*NTILES] (w, fp16)
// -> fp32 stage. Each of the 8 warps owns one 16-row stripe.
template <int KTILES, int NTILES, int LDB, int LDS>
__device__ __forceinline__ void mma_layer(const __half* act, const __half* w,
                                          float* stage, int warp) {
    wmma::fragment<wmma::accumulator, 16, 16, 16, float> acc[NTILES];
#pragma unroll
    for (int n = 0; n < NTILES; n++) wmma::fill_fragment(acc[n], 0.0f);
#pragma unroll
    for (int k = 0; k < KTILES; k++) {
        wmma::fragment<wmma::matrix_a, 16, 16, 16, __half, wmma::row_major> a;
        wmma::load_matrix_sync(a, act + warp * 16 * 72 + k * 16, 72);
#pragma unroll
        for (int n = 0; n < NTILES; n++) {
            wmma::fragment<wmma::matrix_b, 16, 16, 16, __half, wmma::col_major> b;
            wmma::load_matrix_sync(b, w + n * 16 * LDB + k * 16, LDB);
            wmma::mma_sync(acc[n], a, b, acc[n]);
        }
    }
#pragma unroll
    for (int n = 0; n < NTILES; n++)
        wmma::store_matrix_sync(stage + warp * 16 * LDS + n * 16, acc[n], LDS,
                                wmma::mem_row_major);
}

}  // namespace

__global__ void __launch_bounds__(THREADS, 2)
nerf_fused_kernel(const float* __restrict__ hash, const float* __restrict__ sh,
                  const float* __restrict__ d0, const float* __restrict__ d1,
                  const float* __restrict__ c0, const float* __restrict__ c1,
                  const float* __restrict__ c2, const float* __restrict__ c3,
                  float* __restrict__ out, int n_tiles) {
    extern __shared__ char smem_raw[];
    SmemLayout& S = *reinterpret_cast<SmemLayout*>(smem_raw);
    const int tid  = threadIdx.x;
    const int warp = tid >> 5;

    // ---- Stage all weights to SMEM fp16 once per CTA (persistent grid) ----
    // B col-major: element (k, n) at w[n * ldb + k]; W is [out, in] row-major,
    // so B(k,n) = W[n*K + k] -> copy rows contiguously.
    for (int i = tid; i < 64 * 32; i += THREADS)
        S.w_d0[(i >> 5) * 40 + (i & 31)] = __float2half(d0[i]);
    for (int i = tid; i < 16 * 64; i += THREADS)
        S.w_d1[(i >> 6) * 72 + (i & 63)] = __float2half(d1[i]);
    for (int i = tid; i < 64 * 32; i += THREADS) {
        int n = i >> 5, k = i & 31;
        S.w_c0[n * 40 + k] = __float2half(k < 31 ? c0[n * 31 + k] : 0.0f);
    }
    for (int i = tid; i < 64 * 64; i += THREADS) {
        int n = i >> 6, k = i & 63;
        S.w_c1[n * 72 + k] = __float2half(c1[i]);
        S.w_c2[n * 72 + k] = __float2half(c2[i]);
    }
    for (int i = tid; i < 16 * 64; i += THREADS) {
        int n = i >> 6, k = i & 63;
        S.w_c3[n * 72 + k] = __float2half(n < 3 ? c3[n * 64 + k] : 0.0f);
    }
    __syncthreads();

    for (int tile = blockIdx.x; tile < n_tiles; tile += gridDim.x) {
        const size_t row0 = (size_t)tile * TILE_M;

        // hash_feat tile [128 x 32] -> act fp16 (coalesced fp32 reads)
        for (int i = tid; i < TILE_M * 32; i += THREADS) {
            int p = i >> 5, k = i & 31;
            S.act[p * 72 + k] = __float2half(hash[(row0 + p) * 32 + k]);
        }
        __syncthreads();

        // h = relu(hash @ d0^T) : [128x32]x[32x64]
        mma_layer<2, 4, 40, 64>(S.act, S.w_d0, S.stage, warp);
        __syncthreads();
        for (int i = tid; i < TILE_M * 64; i += THREADS)
            S.act[(i >> 6) * 72 + (i & 63)] = __float2half(fmaxf(S.stage[i], 0.0f));
        __syncthreads();

        // i = h @ d1^T : [128x64]x[64x16], NO relu. col0 = sigma, cols1..15 = density
        mma_layer<4, 1, 72, 16>(S.act, S.w_d1, S.stage, warp);
        __syncthreads();

        // act <- [sh (16) | density (15) | 0], sigma saved
        for (int i = tid; i < TILE_M * 32; i += THREADS) {
            int p = i >> 5, c = i & 31;
            float v;
            if (c < 16)      v = sh[(row0 + p) * 16 + c];
            else if (c < 31) v = S.stage[p * 16 + (c - 15)];
            else             v = 0.0f;
            S.act[p * 72 + c] = __float2half(v);
        }
        if (tid < TILE_M) S.sigma[tid] = S.stage[tid * 16];
        __syncthreads();

        // x = relu(x @ c0^T) : [128x32]x[32x64]
        mma_layer<2, 4, 40, 64>(S.act, S.w_c0, S.stage, warp);
        __syncthreads();
        for (int i = tid; i < TILE_M * 64; i += THREADS)
            S.act[(i >> 6) * 72 + (i & 63)] = __float2half(fmaxf(S.stage[i], 0.0f));
        __syncthreads();

        // x = relu(x @ c1^T) : [128x64]x[64x64]
        mma_layer<4, 4, 72, 64>(S.act, S.w_c1, S.stage, warp);
        __syncthreads();
        for (int i = tid; i < TILE_M * 64; i += THREADS)
            S.act[(i >> 6) * 72 + (i & 63)] = __float2half(fmaxf(S.stage[i], 0.0f));
        __syncthreads();

        // x = relu(x @ c2^T)
        mma_layer<4, 4, 72, 64>(S.act, S.w_c2, S.stage, warp);
        __syncthreads();
        for (int i = tid; i < TILE_M * 64; i += THREADS)
            S.act[(i >> 6) * 72 + (i & 63)] = __float2half(fmaxf(S.stage[i], 0.0f));
        __syncthreads();

        // color = x @ c3^T : [128x64]x[64x16(3 real)], no relu
        mma_layer<4, 1, 72, 16>(S.act, S.w_c3, S.stage, warp);
        __syncthreads();

        // out[p] = {color0, color1, color2, sigma} (float4, coalesced)
        if (tid < TILE_M) {
            float4 o;
            o.x = S.stage[tid * 16 + 0];
            o.y = S.stage[tid * 16 + 1];
            o.z = S.stage[tid * 16 + 2];
            o.w = S.sigma[tid];
            reinterpret_cast<float4*>(out)[row0 + tid] = o;
        }
        __syncthreads();
    }
}

extern "C" void kernel_launch(void* const* d_in, const int* in_sizes, int n_in,
                              void* d_out, int out_size) {
    const float* hash = (const float*)d_in[0];  // [N, 32]
    const float* sh   = (const float*)d_in[1];  // [N, 16]
    const float* d0   = (const float*)d_in[2];  // [64, 32]
    const float* d1   = (const float*)d_in[3];  // [16, 64]
    const float* c0   = (const float*)d_in[4];  // [64, 31]
    const float* c1   = (const float*)d_in[5];  // [64, 64]
    const float* c2   = (const float*)d_in[6];  // [64, 64]
    const float* c3   = (const float*)d_in[7];  // [3, 64]
    float* out = (float*)d_out;                 // [N, 4]

    const int n       = in_sizes[0] / 32;
    const int n_tiles = n / TILE_M;  // N = 2097152 -> 16384 tiles

    cudaFuncSetAttribute(nerf_fused_kernel,
                         cudaFuncAttributeMaxDynamicSharedMemorySize,
                         (int)sizeof(SmemLayout));

    int grid = 296;  // 2 CTAs per SM (148 SMs), persistent over tiles
    if (grid > n_tiles) grid = n_tiles;

    nerf_fused_kernel<<<grid, THREADS, sizeof(SmemLayout)>>>(
        hash, sh, d0, d1, c0, c1, c2, c3, out, n_tiles);
}

// round 2
// speedup vs baseline: 2.2694x; 2.2694x over previous
#include <cuda_runtime.h>
#include <cuda_fp16.h>
#include <mma.h>

using namespace nvcuda;

namespace {

constexpr int TILE_M  = 128;
constexpr int THREADS = 256;
constexpr int NWARP   = 8;

// All tile-loop state is warp-private: warp w owns act rows [16w, 16w+16),
// stage[w], sigma[w]. No block-level synchronization needed after weight
// staging -> warps run free.
struct SmemLayout {
    __half act[TILE_M * 72];     // 18432 B, ld=72 (144B rows, 16B aligned)
    float  stage[NWARP][16 * 16];// 8192 B, per-warp f32 staging (d1/c3 out)
    float  sigma[NWARP][16];     // 512 B
    __half w_d0[64 * 40];        // B col-major: (k,n) at n*ld + k
    __half w_d1[16 * 72];
    __half w_c0[64 * 40];
    __half w_c1[64 * 72];
    __half w_c2[64 * 72];
    __half w_c3[16 * 72];
};  // ~59 KB -> 2 CTAs/SM

// [16 x 16*KT] @ [16*KT x 16*NT] with relu fused in registers; half result
// written straight back to act (in-place safe: all A-frags loaded first).
template <int KT, int NT, int LDB>
__device__ __forceinline__ void layer_relu(const __half* __restrict__ act_in,
                                           const __half* __restrict__ w,
                                           __half* __restrict__ act_out) {
    wmma::fragment<wmma::matrix_a, 16, 16, 16, __half, wmma::row_major> a[KT];
#pragma unroll
    for (int k = 0; k < KT; k++)
        wmma::load_matrix_sync(a[k], act_in + k * 16, 72);
#pragma unroll
    for (int n = 0; n < NT; n++) {
        wmma::fragment<wmma::accumulator, 16, 16, 16, float> acc;
        wmma::fill_fragment(acc, 0.0f);
#pragma unroll
        for (int k = 0; k < KT; k++) {
            wmma::fragment<wmma::matrix_b, 16, 16, 16, __half, wmma::col_major> b;
            wmma::load_matrix_sync(b, w + n * 16 * LDB + k * 16, LDB);
            wmma::mma_sync(acc, a[k], b, acc);
        }
        // relu + f32->f16 in registers (identical acc coordinate mapping)
        wmma::fragment<wmma::accumulator, 16, 16, 16, __half> h;
#pragma unroll
        for (int e = 0; e < acc.num_elements; e++)
            h.x[e] = __float2half(fmaxf(acc.x[e], 0.0f));
        wmma::store_matrix_sync(act_out + n * 16, h, 72, wmma::mem_row_major);
    }
}

// [16 x 16*KT] @ [16*KT x 16], f32 result to per-warp stage (no relu).
template <int KT, int LDB>
__device__ __forceinline__ void layer_f32(const __half* __restrict__ act_in,
                                          const __half* __restrict__ w,
                                          float* __restrict__ stg) {
    wmma::fragment<wmma::matrix_a, 16, 16, 16, __half, wmma::row_major> a[KT];
#pragma unroll
    for (int k = 0; k < KT; k++)
        wmma::load_matrix_sync(a[k], act_in + k * 16, 72);
    wmma::fragment<wmma::accumulator, 16, 16, 16, float> acc;
    wmma::fill_fragment(acc, 0.0f);
#pragma unroll
    for (int k = 0; k < KT; k++) {
        wmma::fragment<wmma::matrix_b, 16, 16, 16, __half, wmma::col_major> b;
        wmma::load_matrix_sync(b, w + k * 16, LDB);
        wmma::mma_sync(acc, a[k], b, acc);
    }
    wmma::store_matrix_sync(stg, acc, 16, wmma::mem_row_major);
}

}  // namespace

__global__ void __launch_bounds__(THREADS, 2)
nerf_fused_kernel(const float* __restrict__ hash, const float* __restrict__ sh,
                  const float* __restrict__ d0, const float* __restrict__ d1,
                  const float* __restrict__ c0, const float* __restrict__ c1,
                  const float* __restrict__ c2, const float* __restrict__ c3,
                  float* __restrict__ out, int n_tiles) {
    extern __shared__ char smem_raw[];
    SmemLayout& S = *reinterpret_cast<SmemLayout*>(smem_raw);
    const int tid  = threadIdx.x;
    const int warp = tid >> 5;
    const int lane = tid & 31;

    // ---- Stage all weights to SMEM fp16 once per CTA ----
    for (int i = tid; i < 64 * 32; i += THREADS)
        S.w_d0[(i >> 5) * 40 + (i & 31)] = __float2half(d0[i]);
    for (int i = tid; i < 16 * 64; i += THREADS)
        S.w_d1[(i >> 6) * 72 + (i & 63)] = __float2half(d1[i]);
    for (int i = tid; i < 64 * 32; i += THREADS) {
        int n = i >> 5, k = i & 31;
        S.w_c0[n * 40 + k] = __float2half(k < 31 ? c0[n * 31 + k] : 0.0f);
    }
    for (int i = tid; i < 64 * 64; i += THREADS) {
        int n = i >> 6, k = i & 63;
        S.w_c1[n * 72 + k] = __float2half(c1[i]);
        S.w_c2[n * 72 + k] = __float2half(c2[i]);
    }
    for (int i = tid; i < 16 * 64; i += THREADS) {
        int n = i >> 6, k = i & 63;
        S.w_c3[n * 72 + k] = __float2half(n < 3 ? c3[n * 64 + k] : 0.0f);
    }
    __syncthreads();  // the ONLY block barrier

    __half* actw = S.act + warp * 16 * 72;
    float*  stg  = S.stage[warp];
    float*  sig  = S.sigma[warp];
    const float4* hash4 = reinterpret_cast<const float4*>(hash);
    float4* out4 = reinterpret_cast<float4*>(out);

    for (int tile = blockIdx.x; tile < n_tiles; tile += gridDim.x) {
        const size_t row0 = (size_t)tile * TILE_M + warp * 16;

        // hash tile rows [row0, row0+16) x 32 -> act fp16 (128B/row coalesced)
#pragma unroll
        for (int i = lane; i < 128; i += 32) {
            int r = i >> 3, c = i & 7;
            float4 v = hash4[(row0 + r) * 8 + c];
            __half2* dst = reinterpret_cast<__half2*>(actw + r * 72 + c * 4);
            dst[0] = __floats2half2_rn(v.x, v.y);
            dst[1] = __floats2half2_rn(v.z, v.w);
        }
        __syncwarp();

        // h = relu(hash @ d0^T)
        layer_relu<2, 4, 40>(actw, S.w_d0, actw);
        __syncwarp();

        // i = h @ d1^T  (col0 = sigma, cols 1..15 = density)
        layer_f32<4, 72>(actw, S.w_d1, stg);
        __syncwarp();

        if (lane < 16) sig[lane] = stg[lane * 16];
        // act <- [sh(16) | density(15) | 0]
#pragma unroll
        for (int i = lane; i < 16 * 32; i += 32) {
            int r = i >> 5, c = i & 31;
            float v;
            if (c < 16)      v = sh[(row0 + r) * 16 + c];
            else if (c < 31) v = stg[r * 16 + (c - 15)];
            else             v = 0.0f;
            actw[r * 72 + c] = __float2half(v);
        }
        __syncwarp();

        layer_relu<2, 4, 40>(actw, S.w_c0, actw);
        __syncwarp();
        layer_relu<4, 4, 72>(actw, S.w_c1, actw);
        __syncwarp();
        layer_relu<4, 4, 72>(actw, S.w_c2, actw);
        __syncwarp();

        // color = x @ c3^T
        layer_f32<4, 72>(actw, S.w_c3, stg);
        __syncwarp();

        if (lane < 16) {
            float4 o;
            o.x = stg[lane * 16 + 0];
            o.y = stg[lane * 16 + 1];
            o.z = stg[lane * 16 + 2];
            o.w = sig[lane];
            out4[row0 + lane] = o;
        }
        __syncwarp();
    }
}

extern "C" void kernel_launch(void* const* d_in, const int* in_sizes, int n_in,
                              void* d_out, int out_size) {
    const float* hash = (const float*)d_in[0];  // [N, 32]
    const float* sh   = (const float*)d_in[1];  // [N, 16]
    const float* d0   = (const float*)d_in[2];  // [64, 32]
    const float* d1   = (const float*)d_in[3];  // [16, 64]
    const float* c0   = (const float*)d_in[4];  // [64, 31]
    const float* c1   = (const float*)d_in[5];  // [64, 64]
    const float* c2   = (const float*)d_in[6];  // [64, 64]
    const float* c3   = (const float*)d_in[7];  // [3, 64]
    float* out = (float*)d_out;                 // [N, 4]

    const int n       = in_sizes[0] / 32;
    const int n_tiles = n / TILE_M;  // 16384

    cudaFuncSetAttribute(nerf_fused_kernel,
                         cudaFuncAttributeMaxDynamicSharedMemorySize,
                         (int)sizeof(SmemLayout));

    int grid = 296;  // persistent, 2 CTAs/SM
    if (grid > n_tiles) grid = n_tiles;

    nerf_fused_kernel<<<grid, THREADS, sizeof(SmemLayout)>>>(
        hash, sh, d0, d1, c0, c1, c2, c3, out, n_tiles);
}

// round 3
// speedup vs baseline: 3.1972x; 1.4088x over previous
#include <cuda_runtime.h>
#include <cuda_fp16.h>
#include <mma.h>

using namespace nvcuda;

namespace {

constexpr int THREADS  = 256;
constexpr int NWARP    = 8;
constexpr int MT       = 2;              // m-tiles (16 rows) per warp
constexpr int WARP_M   = 16 * MT;        // 32 rows per warp
constexpr int CTA_M    = NWARP * WARP_M; // 256 rows per CTA

// Warp-private everything -> no block barriers in the tile loop.
// f32 staging for d1/c3 outputs lives INSIDE dead act columns (halves 32..63,
// 64B offset, 32B-aligned, ld = 36 floats = 144B row stride).
struct SmemLayout {
    __half act[NWARP * WARP_M * 72];  // 36864 B
    float  sigma[NWARP][WARP_M];      //  1024 B
    __half w_d0[64 * 40];             //  5120 B  (B col-major: (k,n) at n*ld+k)
    __half w_d1[16 * 72];             //  2304 B
    __half w_c0[64 * 40];             //  5120 B
    __half w_c1[64 * 72];             //  9216 B
    __half w_c2[64 * 72];             //  9216 B
    __half w_c3[16 * 72];             //  2304 B
};  // 71168 B -> 3 CTAs/SM

// [32 x 16KT] @ [16KT x 16NT], relu fused in registers, half result back to
// act. B frags loaded ONCE per n and reused by both m-tiles. In-place safe:
// all A frags register-resident before any store.
template <int KT, int NT, int LDB>
__device__ __forceinline__ void layer_relu(const __half* __restrict__ act_in,
                                           const __half* __restrict__ w,
                                           __half* __restrict__ act_out) {
    wmma::fragment<wmma::matrix_a, 16, 16, 16, __half, wmma::row_major> a[MT][KT];
#pragma unroll
    for (int m = 0; m < MT; m++)
#pragma unroll
        for (int k = 0; k < KT; k++)
            wmma::load_matrix_sync(a[m][k], act_in + m * 16 * 72 + k * 16, 72);
#pragma unroll
    for (int n = 0; n < NT; n++) {
        wmma::fragment<wmma::matrix_b, 16, 16, 16, __half, wmma::col_major> b[KT];
#pragma unroll
        for (int k = 0; k < KT; k++)
            wmma::load_matrix_sync(b[k], w + n * 16 * LDB + k * 16, LDB);
#pragma unroll
        for (int m = 0; m < MT; m++) {
            wmma::fragment<wmma::accumulator, 16, 16, 16, float> acc;
            wmma::fill_fragment(acc, 0.0f);
#pragma unroll
            for (int k = 0; k < KT; k++)
                wmma::mma_sync(acc, a[m][k], b[k], acc);
            wmma::fragment<wmma::accumulator, 16, 16, 16, __half> h;
#pragma unroll
            for (int e = 0; e < acc.num_elements; e++)
                h.x[e] = __float2half(fmaxf(acc.x[e], 0.0f));
            wmma::store_matrix_sync(act_out + m * 16 * 72 + n * 16, h, 72,
                                    wmma::mem_row_major);
        }
    }
}

// [32 x 16KT] @ [16KT x 16], f32 result stored into dead act cols (halves
// 32..63) of each m-tile's own rows. Safe: A frags loaded before stores;
// those smem halves are not read afterwards as layer input.
template <int KT>
__device__ __forceinline__ void layer_f32(const __half* __restrict__ act_in,
                                          const __half* __restrict__ w,
                                          __half* __restrict__ act_base) {
    wmma::fragment<wmma::matrix_a, 16, 16, 16, __half, wmma::row_major> a[MT][KT];
#pragma unroll
    for (int m = 0; m < MT; m++)
#pragma unroll
        for (int k = 0; k < KT; k++)
            wmma::load_matrix_sync(a[m][k], act_in + m * 16 * 72 + k * 16, 72);
    wmma::fragment<wmma::matrix_b, 16, 16, 16, __half, wmma::col_major> b[KT];
#pragma unroll
    for (int k = 0; k < KT; k++)
        wmma::load_matrix_sync(b[k], w + k * 16, 72);
#pragma unroll
    for (int m = 0; m < MT; m++) {
        wmma::fragment<wmma::accumulator, 16, 16, 16, float> acc;
        wmma::fill_fragment(acc, 0.0f);
#pragma unroll
        for (int k = 0; k < KT; k++)
            wmma::mma_sync(acc, a[m][k], b[k], acc);
        float* stg = reinterpret_cast<float*>(act_base + m * 16 * 72 + 32);
        wmma::store_matrix_sync(stg, acc, 36, wmma::mem_row_major);
    }
}

}  // namespace

__global__ void __launch_bounds__(THREADS, 3)
nerf_fused_kernel(const float* __restrict__ hash, const float* __restrict__ sh,
                  const float* __restrict__ d0, const float* __restrict__ d1,
                  const float* __restrict__ c0, const float* __restrict__ c1,
                  const float* __restrict__ c2, const float* __restrict__ c3,
                  float* __restrict__ out, int n_tiles) {
    extern __shared__ char smem_raw[];
    SmemLayout& S = *reinterpret_cast<SmemLayout*>(smem_raw);
    const int tid  = threadIdx.x;
    const int warp = tid >> 5;
    const int lane = tid & 31;

    // ---- Stage all weights to SMEM fp16 once per CTA ----
    for (int i = tid; i < 64 * 32; i += THREADS)
        S.w_d0[(i >> 5) * 40 + (i & 31)] = __float2half(d0[i]);
    for (int i = tid; i < 16 * 64; i += THREADS)
        S.w_d1[(i >> 6) * 72 + (i & 63)] = __float2half(d1[i]);
    for (int i = tid; i < 64 * 32; i += THREADS) {
        int n = i >> 5, k = i & 31;
        S.w_c0[n * 40 + k] = __float2half(k < 31 ? c0[n * 31 + k] : 0.0f);
    }
    for (int i = tid; i < 64 * 64; i += THREADS) {
        int n = i >> 6, k = i & 63;
        S.w_c1[n * 72 + k] = __float2half(c1[i]);
        S.w_c2[n * 72 + k] = __float2half(c2[i]);
    }
    for (int i = tid; i < 16 * 64; i += THREADS) {
        int n = i >> 6, k = i & 63;
        S.w_c3[n * 72 + k] = __float2half(n < 3 ? c3[n * 64 + k] : 0.0f);
    }
    __syncthreads();  // the ONLY block barrier

    __half* actw = S.act + warp * WARP_M * 72;
    float*  sig  = S.sigma[warp];
    const float4* hash4 = reinterpret_cast<const float4*>(hash);
    float4* out4 = reinterpret_cast<float4*>(out);

    for (int tile = blockIdx.x; tile < n_tiles; tile += gridDim.x) {
        const size_t row0 = (size_t)tile * CTA_M + warp * WARP_M;

        // hash rows [row0, row0+32) x 32 -> act fp16 (128B/row coalesced)
#pragma unroll
        for (int i = lane; i < WARP_M * 8; i += 32) {
            int r = i >> 3, c = i & 7;
            float4 v = hash4[(row0 + r) * 8 + c];
            __half2* dst = reinterpret_cast<__half2*>(actw + r * 72 + c * 4);
            dst[0] = __floats2half2_rn(v.x, v.y);
            dst[1] = __floats2half2_rn(v.z, v.w);
        }
        __syncwarp();

        // h = relu(hash @ d0^T) : [32x32]x[32x64]
        layer_relu<2, 4, 40>(actw, S.w_d0, actw);
        __syncwarp();

        // i = h @ d1^T : [32x64]x[64x16] -> f32 stage in dead act cols
        layer_f32<4>(actw, S.w_d1, actw);
        __syncwarp();

        // sigma + pack act <- [sh(16) | density(15) | 0]
        if (lane < WARP_M) {
            const float* stg =
                reinterpret_cast<const float*>(actw + (lane >> 4) * 16 * 72 + 32);
            sig[lane] = stg[(lane & 15) * 36];
        }
#pragma unroll
        for (int i = lane; i < WARP_M * 32; i += 32) {
            int r = i >> 5, c = i & 31;
            const float* stg =
                reinterpret_cast<const float*>(actw + (r >> 4) * 16 * 72 + 32);
            float v;
            if (c < 16)      v = sh[(row0 + r) * 16 + c];
            else if (c < 31) v = stg[(r & 15) * 36 + (c - 15)];
            else             v = 0.0f;
            actw[r * 72 + c] = __float2half(v);
        }
        __syncwarp();

        layer_relu<2, 4, 40>(actw, S.w_c0, actw);  // [32x32]x[32x64]
        __syncwarp();
        layer_relu<4, 4, 72>(actw, S.w_c1, actw);  // [32x64]x[64x64]
        __syncwarp();
        layer_relu<4, 4, 72>(actw, S.w_c2, actw);
        __syncwarp();

        // color = x @ c3^T -> f32 stage in dead act cols
        layer_f32<4>(actw, S.w_c3, actw);
        __syncwarp();

        if (lane < WARP_M) {
            const float* stg =
                reinterpret_cast<const float*>(actw + (lane >> 4) * 16 * 72 + 32);
            int r = lane & 15;
            float4 o;
            o.x = stg[r * 36 + 0];
            o.y = stg[r * 36 + 1];
            o.z = stg[r * 36 + 2];
            o.w = sig[lane];
            out4[row0 + lane] = o;
        }
        __syncwarp();
    }
}

extern "C" void kernel_launch(void* const* d_in, const int* in_sizes, int n_in,
                              void* d_out, int out_size) {
    const float* hash = (const float*)d_in[0];  // [N, 32]
    const float* sh   = (const float*)d_in[1];  // [N, 16]
    const float* d0   = (const float*)d_in[2];  // [64, 32]
    const float* d1   = (const float*)d_in[3];  // [16, 64]
    const float* c0   = (const float*)d_in[4];  // [64, 31]
    const float* c1   = (const float*)d_in[5];  // [64, 64]
    const float* c2   = (const float*)d_in[6];  // [64, 64]
    const float* c3   = (const float*)d_in[7];  // [3, 64]
    float* out = (float*)d_out;                 // [N, 4]

    const int n       = in_sizes[0] / 32;
    const int n_tiles = n / CTA_M;  // 2097152/256 = 8192

    cudaFuncSetAttribute(nerf_fused_kernel,
                         cudaFuncAttributeMaxDynamicSharedMemorySize,
                         (int)sizeof(SmemLayout));

    int grid = 148 * 3;  // persistent, 3 CTAs/SM
    if (grid > n_tiles) grid = n_tiles;

    nerf_fused_kernel<<<grid, THREADS, sizeof(SmemLayout)>>>(
        hash, sh, d0, d1, c0, c1, c2, c3, out, n_tiles);
}